// round 10
// baseline (speedup 1.0000x reference)
#include <cuda_runtime.h>

#define NB 256
#define NT 256

__device__ float        g_partials[NB];
__device__ unsigned int g_bar;   // monotonic ticket counter (never reset)

__global__ void __launch_bounds__(NT, 2)
ril_fused_kernel(const float* __restrict__ x,
                 const float* __restrict__ weights,
                 const float* __restrict__ min_vals,
                 const float* __restrict__ max_vals,
                 const int* __restrict__ start_pos,
                 const int* __restrict__ offsets,
                 const int* __restrict__ sizes,
                 const int* __restrict__ out_mask,
                 float* __restrict__ out,
                 int B, int D, int G, int Wn, int OUTN, int total)
{
    // Shared: G floats (min_vals) then G int4 (packed {max,start,off,size})
    extern __shared__ float smv[];
    int4* stab = (int4*)(smv + G);

    const int lane = threadIdx.x & 31;
    const int w    = threadIdx.x >> 5;
    const float inv_b = 1.0f / (float)B;

    for (int i = threadIdx.x; i < G; i += NT) {
        smv[i] = __ldg(&min_vals[i]);
        int4 e;
        e.x = __float_as_int(__ldg(&max_vals[i]));
        e.y = __ldg(&start_pos[i]);
        e.z = __ldg(&offsets[i]);
        e.w = __ldg(&sizes[i]);
        stab[i] = e;
    }
    __syncthreads();

    // ---- Phase 1: quad-cooperative. 4 lanes share one float4 chunk (4 cols).
    // Lane q loads rows q, q+4, ... ; quad shfl-reduce; each lane finishes 1 col.
    float acc = 0.0f;
    const int qlane   = threadIdx.x & 3;
    const int nchunk  = D >> 2;
    const int qstride = ((int)gridDim.x * NT) >> 2;
    const int qid     = (blockIdx.x * NT + threadIdx.x) >> 2;

    for (int chunk = qid; chunk < nchunk; chunk += qstride) {
        float4 p = make_float4(0.f, 0.f, 0.f, 0.f);
        for (int b = qlane; b < B; b += 4) {
            const float4 xv = __ldg((const float4*)(x + (size_t)b * D) + chunk);
            p.x += xv.x; p.y += xv.y; p.z += xv.z; p.w += xv.w;
        }
        // quad reduce (xor 1 then xor 2): all 4 lanes end with full row-sum
        #pragma unroll
        for (int m = 1; m <= 2; m <<= 1) {
            p.x += __shfl_xor_sync(0xffffffffu, p.x, m);
            p.y += __shfl_xor_sync(0xffffffffu, p.y, m);
            p.z += __shfl_xor_sync(0xffffffffu, p.z, m);
            p.w += __shfl_xor_sync(0xffffffffu, p.w, m);
        }
        const float sv = (qlane == 0) ? p.x : (qlane == 1) ? p.y
                        : (qlane == 2) ? p.z : p.w;
        const float vv = sv * inv_b;
        const int col = chunk * 4 + qlane;

        // searchsorted(min_vals, v, 'right') - 1
        int lo = 0, hi = G;
        while (lo < hi) {
            int mid = (lo + hi) >> 1;
            if (smv[mid] <= vv) lo = mid + 1; else hi = mid;
        }
        const int g  = lo - 1;
        const int gc = min(max(g, 0), G - 1);

        const int4 e = stab[gc];
        const float mx  = __int_as_float(e.x);
        bool in_range = (g >= 0) && (vv >= smv[gc]) && (vv <= mx);
        int pos = col - e.y;
        bool valid = in_range && (pos >= 0) && (pos < e.w);
        int widx = e.z + pos;
        widx = min(max(widx, 0), Wn - 1);
        float wv = valid ? __ldg(&weights[widx]) : 0.0f;
        acc += vv * wv;
    }

    // Scalar tail (D % 4 != 0), block 0 only
    if (blockIdx.x == 0) {
        for (int col = nchunk * 4 + threadIdx.x; col < D; col += NT) {
            float s = 0.0f;
            for (int b = 0; b < B; ++b) s += x[(size_t)b * D + col];
            const float vv = s * inv_b;
            int lo = 0, hi = G;
            while (lo < hi) {
                int mid = (lo + hi) >> 1;
                if (smv[mid] <= vv) lo = mid + 1; else hi = mid;
            }
            const int g  = lo - 1;
            const int gc = min(max(g, 0), G - 1);
            const int4 e = stab[gc];
            bool in_range = (g >= 0) && (vv >= smv[gc]) && (vv <= __int_as_float(e.x));
            int pos = col - e.y;
            bool valid = in_range && (pos >= 0) && (pos < e.w);
            int widx = min(max(e.z + pos, 0), Wn - 1);
            acc += vv * (valid ? weights[widx] : 0.0f);
        }
    }

    // ---- Block reduce ----
    #pragma unroll
    for (int o = 16; o > 0; o >>= 1)
        acc += __shfl_down_sync(0xffffffffu, acc, o);
    __shared__ float red[NT / 32];
    if (lane == 0) red[w] = acc;
    __syncthreads();
    if (threadIdx.x == 0) {
        float p = 0.0f;
        #pragma unroll
        for (int k = 0; k < NT / 32; ++k) p += red[k];
        g_partials[blockIdx.x] = p;
    }

    // ---- Device-wide ticket barrier (monotonic; survives graph replays) ----
    if (threadIdx.x == 0) {
        __threadfence();
        unsigned int arrival = atomicAdd(&g_bar, 1u) + 1u;
        unsigned int target  = ((arrival - 1u) / gridDim.x + 1u) * gridDim.x;
        unsigned int c;
        do {
            asm volatile("ld.acquire.gpu.u32 %0, [%1];" : "=r"(c) : "l"(&g_bar));
        } while (c < target);
    }
    __syncthreads();

    // ---- Phase 2: all blocks sum partials with a fixed deterministic tree ----
    float a2 = 0.0f;
    for (int i = threadIdx.x; i < (int)gridDim.x; i += NT)
        a2 += *(volatile float*)&g_partials[i];
    #pragma unroll
    for (int o = 16; o > 0; o >>= 1)
        a2 += __shfl_down_sync(0xffffffffu, a2, o);
    __shared__ float red2[NT / 32];
    __shared__ float s_val;
    if (lane == 0) red2[w] = a2;
    __syncthreads();
    if (threadIdx.x == 0) {
        float s = 0.0f;
        #pragma unroll
        for (int k = 0; k < NT / 32; ++k) s += red2[k];
        s_val = s;
    }
    __syncthreads();
    const float s = s_val;

    // ---- Output: each block writes its contiguous slice, vectorized ----
    const int per = (total + (int)gridDim.x - 1) / (int)gridDim.x;
    const int j0  = blockIdx.x * per;
    const int j1  = min(j0 + per, total);

    if ((j0 & 3) == 0 && (per & 3) == 0 && (OUTN & 3) == 0) {
        for (int j = j0 + threadIdx.x * 4; j < j1; j += NT * 4) {
            float4 o4 = make_float4(0.f, 0.f, 0.f, 0.f);
            if (j + 3 < OUTN) {
                const int4 m4 = __ldg((const int4*)(out_mask + j));
                o4.x = m4.x ? s : 0.0f;
                o4.y = m4.y ? s : 0.0f;
                o4.z = m4.z ? s : 0.0f;
                o4.w = m4.w ? s : 0.0f;
            }
            *(float4*)(out + j) = o4;
        }
    } else {
        for (int j = j0 + threadIdx.x; j < j1; j += NT) {
            float o = 0.0f;
            if (j < OUTN) o = (__ldg(&out_mask[j]) != 0) ? s : 0.0f;
            out[j] = o;
        }
    }
}

extern "C" void kernel_launch(void* const* d_in, const int* in_sizes, int n_in,
                              void* d_out, int out_size)
{
    const float* x        = (const float*)d_in[0];
    const float* weights  = (const float*)d_in[1];
    const float* min_vals = (const float*)d_in[2];
    const float* max_vals = (const float*)d_in[3];
    const int*   start_p  = (const int*)d_in[4];
    const int*   offsets  = (const int*)d_in[5];
    const int*   sizes    = (const int*)d_in[6];
    const int*   out_mask = (const int*)d_in[7];
    float* out = (float*)d_out;

    int G  = in_sizes[2];
    int Wn = in_sizes[1];
    int D  = Wn / G;
    int B  = in_sizes[0] / D;
    int OUTN = in_sizes[7];

    size_t shmem = (size_t)G * (sizeof(float) + sizeof(int4));
    ril_fused_kernel<<<NB, NT, shmem>>>(
        x, weights, min_vals, max_vals, start_p, offsets, sizes,
        out_mask, out, B, D, G, Wn, OUTN, out_size);
}

// round 11
// speedup vs baseline: 1.0616x; 1.0616x over previous
#include <cuda_runtime.h>

#define NB 256
#define NT 256
#define HOIST_MAX 4096   // max output elems/block prefetched to shared

__device__ float        g_partials[NB];
__device__ unsigned int g_bar;   // monotonic ticket counter (never reset)

__global__ void __launch_bounds__(NT, 2)
ril_fused_kernel(const float* __restrict__ x,
                 const float* __restrict__ weights,
                 const float* __restrict__ min_vals,
                 const float* __restrict__ max_vals,
                 const int* __restrict__ start_pos,
                 const int* __restrict__ offsets,
                 const int* __restrict__ sizes,
                 const int* __restrict__ out_mask,
                 float* __restrict__ out,
                 int B, int D, int G, int Wn, int OUTN, int total)
{
    // Shared: G floats (min_vals) | G int4 (packed {max,start,off,size}) | hoisted mask
    extern __shared__ float smv[];
    int4*  stab  = (int4*)(smv + G);
    float* smask = (float*)(stab + G);

    const int lane = threadIdx.x & 31;
    const int w    = threadIdx.x >> 5;
    const float inv_b = 1.0f / (float)B;

    for (int i = threadIdx.x; i < G; i += NT) {
        smv[i] = __ldg(&min_vals[i]);
        int4 e;
        e.x = __float_as_int(__ldg(&max_vals[i]));
        e.y = __ldg(&start_pos[i]);
        e.z = __ldg(&offsets[i]);
        e.w = __ldg(&sizes[i]);
        stab[i] = e;
    }

    // Hoist this block's out_mask slice to shared as 0.0/1.0 floats (pre-barrier)
    const int per = (total + (int)gridDim.x - 1) / (int)gridDim.x;
    const int j0  = blockIdx.x * per;
    const int j1  = min(j0 + per, total);
    const bool hoist = (per <= HOIST_MAX);
    if (hoist) {
        for (int j = j0 + threadIdx.x; j < j1; j += NT) {
            float m = 0.0f;
            if (j < OUTN) m = (__ldg(&out_mask[j]) != 0) ? 1.0f : 0.0f;
            smask[j - j0] = m;
        }
    }
    __syncthreads();

    const float m0 = smv[0];
    const float mL = smv[G - 1];
    const float inv_step = (mL > m0) ? (float)(G - 1) / (mL - m0) : 0.0f;

    // ---- Phase 1: one column per thread, grid-stride ----
    float acc = 0.0f;
    const int stride = (int)gridDim.x * NT;
    for (int col = blockIdx.x * NT + threadIdx.x; col < D; col += stride) {
        float s = 0.0f;
        #pragma unroll 8
        for (int b = 0; b < B; ++b)
            s += __ldg(x + (size_t)b * D + col);
        const float vv = s * inv_b;

        // searchsorted(min_vals, vv, 'right') - 1 via interpolation + fixup
        int g;
        if (!(vv >= m0)) {
            g = -1;                      // below first bound (or NaN -> invalid)
        } else {
            int gg = (int)floorf((vv - m0) * inv_step);
            gg = min(max(gg, 0), G - 1);
            // predicated fixup (straight-line, <=2 each direction)
            gg -= (smv[gg] > vv) ? 1 : 0;
            gg -= (gg > 0 && smv[gg] > vv) ? 1 : 0;
            gg += (gg + 1 < G && smv[gg + 1] <= vv) ? 1 : 0;
            gg += (gg + 1 < G && smv[gg + 1] <= vv) ? 1 : 0;
            gg = max(gg, 0);
            bool ok = (smv[gg] <= vv) && (gg + 1 >= G || smv[gg + 1] > vv);
            if (!ok) {                   // general fallback (non-uniform grids)
                int lo = 0, hi = G;
                while (lo < hi) {
                    int mid = (lo + hi) >> 1;
                    if (smv[mid] <= vv) lo = mid + 1; else hi = mid;
                }
                gg = lo - 1;
            }
            g = gg;
        }

        const int gc = min(max(g, 0), G - 1);
        const int4 e = stab[gc];
        const float mx = __int_as_float(e.x);
        bool in_range = (g >= 0) && (vv >= smv[gc]) && (vv <= mx);
        int pos = col - e.y;
        bool valid = in_range && (pos >= 0) && (pos < e.w);
        int widx = min(max(e.z + pos, 0), Wn - 1);
        float wv = valid ? __ldg(&weights[widx]) : 0.0f;
        acc += vv * wv;
    }

    // ---- Block reduce ----
    #pragma unroll
    for (int o = 16; o > 0; o >>= 1)
        acc += __shfl_down_sync(0xffffffffu, acc, o);
    __shared__ float red[NT / 32];
    if (lane == 0) red[w] = acc;
    __syncthreads();
    if (threadIdx.x == 0) {
        float p = 0.0f;
        #pragma unroll
        for (int k = 0; k < NT / 32; ++k) p += red[k];
        g_partials[blockIdx.x] = p;
    }

    // ---- Device-wide ticket barrier (monotonic; survives graph replays) ----
    if (threadIdx.x == 0) {
        __threadfence();
        unsigned int arrival = atomicAdd(&g_bar, 1u) + 1u;
        unsigned int target  = ((arrival - 1u) / gridDim.x + 1u) * gridDim.x;
        unsigned int c;
        do {
            asm volatile("ld.acquire.gpu.u32 %0, [%1];" : "=r"(c) : "l"(&g_bar));
        } while (c < target);
    }
    __syncthreads();

    // ---- Phase 2: all blocks sum partials with a fixed deterministic tree ----
    float a2 = 0.0f;
    for (int i = threadIdx.x; i < (int)gridDim.x; i += NT)
        a2 += *(volatile float*)&g_partials[i];
    #pragma unroll
    for (int o = 16; o > 0; o >>= 1)
        a2 += __shfl_down_sync(0xffffffffu, a2, o);
    __shared__ float red2[NT / 32];
    __shared__ float s_val;
    if (lane == 0) red2[w] = a2;
    __syncthreads();
    if (threadIdx.x == 0) {
        float s = 0.0f;
        #pragma unroll
        for (int k = 0; k < NT / 32; ++k) s += red2[k];
        s_val = s;
    }
    __syncthreads();
    const float s = s_val;

    // ---- Output: masked broadcast from shared (no global mask reload) ----
    if (hoist) {
        for (int j = j0 + threadIdx.x; j < j1; j += NT)
            out[j] = s * smask[j - j0];
    } else {
        for (int j = j0 + threadIdx.x; j < j1; j += NT) {
            float o = 0.0f;
            if (j < OUTN) o = (__ldg(&out_mask[j]) != 0) ? s : 0.0f;
            out[j] = o;
        }
    }
}

extern "C" void kernel_launch(void* const* d_in, const int* in_sizes, int n_in,
                              void* d_out, int out_size)
{
    const float* x        = (const float*)d_in[0];
    const float* weights  = (const float*)d_in[1];
    const float* min_vals = (const float*)d_in[2];
    const float* max_vals = (const float*)d_in[3];
    const int*   start_p  = (const int*)d_in[4];
    const int*   offsets  = (const int*)d_in[5];
    const int*   sizes    = (const int*)d_in[6];
    const int*   out_mask = (const int*)d_in[7];
    float* out = (float*)d_out;

    int G  = in_sizes[2];
    int Wn = in_sizes[1];
    int D  = Wn / G;
    int B  = in_sizes[0] / D;
    int OUTN = in_sizes[7];

    int per = (out_size + NB - 1) / NB;
    int hoist_elems = (per <= HOIST_MAX) ? per : 0;
    size_t shmem = (size_t)G * (sizeof(float) + sizeof(int4))
                 + (size_t)hoist_elems * sizeof(float);

    ril_fused_kernel<<<NB, NT, shmem>>>(
        x, weights, min_vals, max_vals, start_p, offsets, sizes,
        out_mask, out, B, D, G, Wn, OUTN, out_size);
}